// round 1
// baseline (speedup 1.0000x reference)
#include <cuda_runtime.h>
#include <math.h>

#define CD 128
#define NMAX 100352
#define EMAX 1700000

// ---------------- device scratch (no allocations allowed) ----------------
__device__ float g_P[(size_t)NMAX * CD];   // GEMM output / logits
__device__ float g_H[(size_t)NMAX * CD];   // hidden activations
__device__ float g_dis[NMAX];              // 1/sqrt(deg)
__device__ int   g_cnt[NMAX];              // incoming-edge counts (excl. self loop)
__device__ int   g_off[NMAX];              // exclusive prefix of counts
__device__ int   g_cur[NMAX];              // fill cursors
__device__ int   g_bkt[EMAX];              // bucketed source node ids
__device__ int   g_part[128];              // scan partials
__device__ float g_Wt[CD * CD];            // transposed weight (Wt[k][c])

// ---------------- small structural kernels ----------------
__global__ void k_zero_cnt(int n) {
    int i = blockIdx.x * blockDim.x + threadIdx.x;
    if (i < n) g_cnt[i] = 0;
}

__global__ void k_count(const int* __restrict__ col, int E) {
    for (int e = blockIdx.x * blockDim.x + threadIdx.x; e < E;
         e += gridDim.x * blockDim.x)
        atomicAdd(&g_cnt[col[e]], 1);
}

__global__ void k_dis(int n) {
    int i = blockIdx.x * blockDim.x + threadIdx.x;
    if (i < n) g_dis[i] = rsqrtf((float)g_cnt[i] + 1.0f);
}

// Hillis-Steele scan, 1024/block. Writes per-block exclusive scan + block sums.
__global__ void k_scan1(int n) {
    __shared__ int s[1024];
    int tid = threadIdx.x;
    int i = blockIdx.x * 1024 + tid;
    int x = (i < n) ? g_cnt[i] : 0;
    s[tid] = x;
    __syncthreads();
    for (int d = 1; d < 1024; d <<= 1) {
        int t = (tid >= d) ? s[tid - d] : 0;
        __syncthreads();
        s[tid] += t;
        __syncthreads();
    }
    if (i < n) g_off[i] = s[tid] - x;            // exclusive within block
    if (tid == 1023) g_part[blockIdx.x] = s[1023];
}

__global__ void k_scan2(int nb) {   // single block of 128 threads, nb <= 128
    __shared__ int s[128];
    int tid = threadIdx.x;
    int x = (tid < nb) ? g_part[tid] : 0;
    s[tid] = x;
    __syncthreads();
    for (int d = 1; d < 128; d <<= 1) {
        int t = (tid >= d) ? s[tid - d] : 0;
        __syncthreads();
        s[tid] += t;
        __syncthreads();
    }
    if (tid < nb) g_part[tid] = s[tid] - x;      // exclusive
}

__global__ void k_scan3(int n) {
    int i = blockIdx.x * blockDim.x + threadIdx.x;
    if (i < n) {
        int v = g_off[i] + g_part[i >> 10];
        g_off[i] = v;
        g_cur[i] = v;
    }
}

__global__ void k_fill(const int* __restrict__ row, const int* __restrict__ col, int E) {
    for (int e = blockIdx.x * blockDim.x + threadIdx.x; e < E;
         e += gridDim.x * blockDim.x) {
        int p = atomicAdd(&g_cur[col[e]], 1);
        g_bkt[p] = row[e];
    }
}

__global__ void k_transpose(const float* __restrict__ W) {
    int i = blockIdx.x * 256 + threadIdx.x;   // 64 blocks * 256 = 16384 = 128*128
    int c = i >> 7, k = i & 127;
    g_Wt[k * CD + c] = W[i];                  // W[c][k] -> Wt[k][c]
}

// ---------------- GEMM: P[i][c] = (dis[i])? * sum_k X[i][k] * Wt[k][c] ----------------
// 128x128 tile per block, 256 threads, each thread 8x8 micro-tile, K chunked by 32.
__global__ void __launch_bounds__(256, 2)
k_gemm(const float* __restrict__ Xext, int useExt, int useDis, int n) {
    __shared__ float Xs[128][36];   // [row][k], padded
    __shared__ float Ws[32][128];   // [k][col]
    const float* __restrict__ X = useExt ? Xext : g_H;

    int row0 = blockIdx.x * 128;
    int tid = threadIdx.x;
    int tx = tid & 15, ty = tid >> 4;

    float acc[8][8];
#pragma unroll
    for (int i = 0; i < 8; i++)
#pragma unroll
        for (int j = 0; j < 8; j++) acc[i][j] = 0.0f;

    for (int kc = 0; kc < 128; kc += 32) {
#pragma unroll
        for (int p = 0; p < 4; p++) {        // load X tile 128x32 (float4)
            int f = tid + p * 256;
            int r = f >> 3, c4 = f & 7;
            float4 v = make_float4(0.f, 0.f, 0.f, 0.f);
            int gr = row0 + r;
            if (gr < n) v = *(const float4*)&X[(size_t)gr * CD + kc + c4 * 4];
            Xs[r][c4 * 4 + 0] = v.x;
            Xs[r][c4 * 4 + 1] = v.y;
            Xs[r][c4 * 4 + 2] = v.z;
            Xs[r][c4 * 4 + 3] = v.w;
        }
#pragma unroll
        for (int p = 0; p < 4; p++) {        // load W tile 32x128 (float4)
            int f = tid + p * 256;
            int k = f >> 5, c4 = f & 31;
            *(float4*)&Ws[k][c4 * 4] = *(const float4*)&g_Wt[(size_t)(kc + k) * CD + c4 * 4];
        }
        __syncthreads();

#pragma unroll 4
        for (int k = 0; k < 32; k++) {
            float a[8];
#pragma unroll
            for (int i = 0; i < 4; i++) {
                a[i]     = Xs[ty * 4 + i][k];
                a[4 + i] = Xs[64 + ty * 4 + i][k];
            }
            float4 b0 = *(const float4*)&Ws[k][tx * 4];
            float4 b1 = *(const float4*)&Ws[k][64 + tx * 4];
#pragma unroll
            for (int i = 0; i < 8; i++) {
                acc[i][0] = fmaf(a[i], b0.x, acc[i][0]);
                acc[i][1] = fmaf(a[i], b0.y, acc[i][1]);
                acc[i][2] = fmaf(a[i], b0.z, acc[i][2]);
                acc[i][3] = fmaf(a[i], b0.w, acc[i][3]);
                acc[i][4] = fmaf(a[i], b1.x, acc[i][4]);
                acc[i][5] = fmaf(a[i], b1.y, acc[i][5]);
                acc[i][6] = fmaf(a[i], b1.z, acc[i][6]);
                acc[i][7] = fmaf(a[i], b1.w, acc[i][7]);
            }
        }
        __syncthreads();
    }

#pragma unroll
    for (int i = 0; i < 8; i++) {
        int r = (i < 4) ? (ty * 4 + i) : (64 + ty * 4 + i - 4);
        int gr = row0 + r;
        if (gr < n) {
            float s = useDis ? g_dis[gr] : 1.0f;
            float4 o0 = make_float4(acc[i][0] * s, acc[i][1] * s, acc[i][2] * s, acc[i][3] * s);
            float4 o1 = make_float4(acc[i][4] * s, acc[i][5] * s, acc[i][6] * s, acc[i][7] * s);
            *(float4*)&g_P[(size_t)gr * CD + tx * 4] = o0;
            *(float4*)&g_P[(size_t)gr * CD + 64 + tx * 4] = o1;
        }
    }
}

// ---------------- gather: H[i] = relu(dis[i]*(P[i] + sum_{j->i} P[j]) + b) ----------------
// one warp per node, float4 per lane (32*4 = 128 channels)
__global__ void k_gather(const float* __restrict__ bias, int n) {
    int w = (blockIdx.x * blockDim.x + threadIdx.x) >> 5;
    if (w >= n) return;
    int lane = threadIdx.x & 31;

    const float4* __restrict__ P4 = (const float4*)g_P;
    float4 acc = P4[(size_t)w * 32 + lane];          // self loop
    int o = g_off[w];
    int c = g_cnt[w];

    int j = 0;
    for (; j + 2 <= c; j += 2) {
        int r0 = g_bkt[o + j];
        int r1 = g_bkt[o + j + 1];
        float4 v0 = P4[(size_t)r0 * 32 + lane];
        float4 v1 = P4[(size_t)r1 * 32 + lane];
        acc.x += v0.x; acc.y += v0.y; acc.z += v0.z; acc.w += v0.w;
        acc.x += v1.x; acc.y += v1.y; acc.z += v1.z; acc.w += v1.w;
    }
    if (j < c) {
        int r0 = g_bkt[o + j];
        float4 v0 = P4[(size_t)r0 * 32 + lane];
        acc.x += v0.x; acc.y += v0.y; acc.z += v0.z; acc.w += v0.w;
    }

    float s = g_dis[w];
    float4 b = *(const float4*)&bias[lane * 4];
    float4 out;
    out.x = fmaxf(fmaf(acc.x, s, b.x), 0.0f);
    out.y = fmaxf(fmaf(acc.y, s, b.y), 0.0f);
    out.z = fmaxf(fmaf(acc.z, s, b.z), 0.0f);
    out.w = fmaxf(fmaf(acc.w, s, b.w), 0.0f);
    ((float4*)g_H)[(size_t)w * 32 + lane] = out;
}

// ---------------- log_softmax over 128 classes, one warp per row ----------------
__global__ void k_logsoftmax(const float* __restrict__ bl, float* __restrict__ out, int n) {
    int w = (blockIdx.x * blockDim.x + threadIdx.x) >> 5;
    if (w >= n) return;
    int lane = threadIdx.x & 31;

    float4 v = *(const float4*)&g_P[(size_t)w * CD + lane * 4];
    float4 b = *(const float4*)&bl[lane * 4];
    v.x += b.x; v.y += b.y; v.z += b.z; v.w += b.w;

    float m = fmaxf(fmaxf(v.x, v.y), fmaxf(v.z, v.w));
#pragma unroll
    for (int d = 16; d; d >>= 1) m = fmaxf(m, __shfl_xor_sync(0xFFFFFFFFu, m, d));

    float s = expf(v.x - m) + expf(v.y - m) + expf(v.z - m) + expf(v.w - m);
#pragma unroll
    for (int d = 16; d; d >>= 1) s += __shfl_xor_sync(0xFFFFFFFFu, s, d);

    float l = m + logf(s);
    float4 o = make_float4(v.x - l, v.y - l, v.z - l, v.w - l);
    *(float4*)&out[(size_t)w * CD + lane * 4] = o;
}

// ---------------- launch ----------------
extern "C" void kernel_launch(void* const* d_in, const int* in_sizes, int n_in,
                              void* d_out, int out_size) {
    const float* x  = (const float*)d_in[0];
    const int*   ei = (const int*)d_in[1];
    const float* b1 = (const float*)d_in[3];
    const float* b2 = (const float*)d_in[5];
    const float* bl = (const float*)d_in[7];
    const float* W1 = (const float*)d_in[2];
    const float* W2 = (const float*)d_in[4];
    const float* Wl = (const float*)d_in[6];

    int n = in_sizes[0] / CD;
    int E = in_sizes[1] / 2;
    const int* row = ei;
    const int* col = ei + E;

    int nb256 = (n + 255) / 256;
    int nbScan = (n + 1023) / 1024;
    int gatherB = (n + 7) / 8;       // (n warps * 32) / 256
    int gemmB = (n + 127) / 128;

    // degree + bucketing (shared by both convs)
    k_zero_cnt<<<nb256, 256>>>(n);
    k_count<<<2048, 256>>>(col, E);
    k_dis<<<nb256, 256>>>(n);
    k_scan1<<<nbScan, 1024>>>(n);
    k_scan2<<<1, 128>>>(nbScan);
    k_scan3<<<nb256, 256>>>(n);
    k_fill<<<2048, 256>>>(row, col, E);

    // conv1
    k_transpose<<<64, 256>>>(W1);
    k_gemm<<<gemmB, 256>>>(x, 1, 1, n);
    k_gather<<<gatherB, 256>>>(b1, n);

    // conv2
    k_transpose<<<64, 256>>>(W2);
    k_gemm<<<gemmB, 256>>>(nullptr, 0, 1, n);
    k_gather<<<gatherB, 256>>>(b2, n);

    // linear + log_softmax
    k_transpose<<<64, 256>>>(Wl);
    k_gemm<<<gemmB, 256>>>(nullptr, 0, 0, n);
    k_logsoftmax<<<gatherB, 256>>>(bl, (float*)d_out, n);
}